// round 6
// baseline (speedup 1.0000x reference)
#include <cuda_runtime.h>
#include <cuda_fp16.h>
#include <cstdint>
#include <math.h>

// Problem constants: q,k,v : [B, S, D] float32
#define BATCH 8
#define SEQ   2048
#define DIM   512

// ---------------------------------------------------------------------------
// Scratch (__device__ globals; no allocation allowed)
// ---------------------------------------------------------------------------
__device__ __half g_qh[(size_t)BATCH * SEQ * DIM];   // Q in fp16
__device__ __half g_kh[(size_t)BATCH * SEQ * DIM];   // K in fp16
__device__ __half g_vt[(size_t)BATCH * DIM * SEQ];   // V transposed (K-major), fp16
__device__ __half g_wh[(size_t)BATCH * SEQ * SEQ];   // softmax weights, fp16

// ---------------------------------------------------------------------------
// fp16 warp-MMA GEMM:  C[b] = alpha * A[b] (MxK, K-major) * B[b]^T (NxK, K-major)
// CTA tile 128x256, BK=64 halves (128B rows, XOR-swizzled), 3-stage cp.async,
// 16 warps (2 in M x 8 in N), warp tile 64x32 from m16n8k16 + ldmatrix.x4.
// 512 threads -> 4 warps/SMSP for latency hiding.
// ---------------------------------------------------------------------------
#define BM 128
#define BN 256
#define BKH 64                               // halves per row-stage (128 bytes)
#define NSTG 3
#define A_BYTES (BM * 128)                   // 16384
#define B_BYTES (BN * 128)                   // 32768
#define STAGE_BYTES (A_BYTES + B_BYTES)      // 49152
#define HGEMM_DSMEM (NSTG * STAGE_BYTES)     // 147456
#define NTHR 512

__device__ __forceinline__ void ldsm_x4(uint32_t r[4], uint32_t addr) {
    asm volatile("ldmatrix.sync.aligned.m8n8.x4.shared.b16 {%0,%1,%2,%3}, [%4];"
                 : "=r"(r[0]), "=r"(r[1]), "=r"(r[2]), "=r"(r[3]) : "r"(addr));
}

__global__ __launch_bounds__(NTHR, 1)
void gemm_h(const __half* __restrict__ A, const __half* __restrict__ B,
            float* __restrict__ C, int M, int N, int Kd, float alpha)
{
    extern __shared__ char smem[];
    const uint32_t smem_b = (uint32_t)__cvta_generic_to_shared(smem);

    const int tid  = threadIdx.x;
    const int wid  = tid >> 5;
    const int lane = tid & 31;
    const int g    = lane >> 2;
    const int tg   = lane & 3;
    const int lr   = lane & 15;     // ldmatrix row-within-16
    const int lc   = lane >> 4;     // ldmatrix 16B-chunk select (0/1)

    const int wm = wid & 1;         // 0..1 (64 rows each)
    const int wn = wid >> 1;        // 0..7 (32 cols each)

    const int bz = blockIdx.z;
    const int n0 = blockIdx.x * BN;
    const int m0 = blockIdx.y * BM;
    const __half* Ab = A + (size_t)bz * M * Kd;
    const __half* Bb = B + (size_t)bz * N * Kd;
    float*        Cb = C + (size_t)bz * M * N;

    float acc[4][4][4];
#pragma unroll
    for (int i = 0; i < 4; i++)
#pragma unroll
        for (int j = 0; j < 4; j++)
#pragma unroll
            for (int r = 0; r < 4; r++)
                acc[i][j][r] = 0.0f;

    const int T = Kd / BKH;

    auto load_stage = [&](int buf, int kt) {
        const int k0 = kt * BKH;
        const uint32_t ab = smem_b + (uint32_t)buf * STAGE_BYTES;
        const uint32_t bb = ab + A_BYTES;
#pragma unroll
        for (int i = 0; i < 2; i++) {              // A: 1024 16B chunks / 512 thr
            int idx = tid + i * NTHR;
            int row = idx >> 3;
            int c   = idx & 7;
            uint32_t d = ab + (uint32_t)(row * 128 + ((c ^ (row & 7)) << 4));
            const __half* s = Ab + (size_t)(m0 + row) * Kd + k0 + c * 8;
            asm volatile("cp.async.cg.shared.global [%0], [%1], 16;" :: "r"(d), "l"(s));
        }
#pragma unroll
        for (int i = 0; i < 4; i++) {              // B: 2048 16B chunks / 512 thr
            int idx = tid + i * NTHR;
            int row = idx >> 3;
            int c   = idx & 7;
            uint32_t d = bb + (uint32_t)(row * 128 + ((c ^ (row & 7)) << 4));
            const __half* s = Bb + (size_t)(n0 + row) * Kd + k0 + c * 8;
            asm volatile("cp.async.cg.shared.global [%0], [%1], 16;" :: "r"(d), "l"(s));
        }
    };

#pragma unroll
    for (int s = 0; s < NSTG - 1; s++) {
        load_stage(s, s);
        asm volatile("cp.async.commit_group;" ::: "memory");
    }

    int cbuf = 0;            // compute buffer
    int lbuf = NSTG - 1;     // next load buffer
    for (int t = 0; t < T; t++) {
        asm volatile("cp.async.wait_group %0;" :: "n"(NSTG - 2) : "memory");
        __syncthreads();

        const int tn = t + NSTG - 1;
        if (tn < T) load_stage(lbuf, tn);
        asm volatile("cp.async.commit_group;" ::: "memory");
        lbuf = (lbuf + 1 == NSTG) ? 0 : lbuf + 1;

        const uint32_t ab = smem_b + (uint32_t)cbuf * STAGE_BYTES;
        const uint32_t bb = ab + A_BYTES;
        cbuf = (cbuf + 1 == NSTG) ? 0 : cbuf + 1;

#pragma unroll
        for (int ks = 0; ks < BKH / 16; ks++) {    // 4 k16 steps
            const int c = ks * 2 + lc;
            uint32_t a[4][4], b[2][4];
#pragma unroll
            for (int mt = 0; mt < 4; mt++) {
                int r = wm * 64 + mt * 16 + lr;
                ldsm_x4(a[mt], ab + (uint32_t)(r * 128 + ((c ^ (r & 7)) << 4)));
            }
#pragma unroll
            for (int pr = 0; pr < 2; pr++) {
                int r = wn * 32 + pr * 16 + lr;
                ldsm_x4(b[pr], bb + (uint32_t)(r * 128 + ((c ^ (r & 7)) << 4)));
            }
#pragma unroll
            for (int mt = 0; mt < 4; mt++)
#pragma unroll
                for (int nt = 0; nt < 4; nt++) {
                    const int pr = nt >> 1, od = nt & 1;
                    asm volatile(
                        "mma.sync.aligned.m16n8k16.row.col.f32.f16.f16.f32 "
                        "{%0,%1,%2,%3}, {%4,%5,%6,%7}, {%8,%9}, {%0,%1,%2,%3};"
                        : "+f"(acc[mt][nt][0]), "+f"(acc[mt][nt][1]),
                          "+f"(acc[mt][nt][2]), "+f"(acc[mt][nt][3])
                        : "r"(a[mt][0]), "r"(a[mt][1]), "r"(a[mt][2]), "r"(a[mt][3]),
                          "r"(b[pr][od]), "r"(b[pr][od + 2]));
                }
        }
    }

    // Epilogue: c0=[g][2tg], c1=[g][2tg+1], c2=[g+8][2tg], c3=[g+8][2tg+1]
#pragma unroll
    for (int mt = 0; mt < 4; mt++) {
        const int row = m0 + wm * 64 + mt * 16 + g;
#pragma unroll
        for (int nt = 0; nt < 4; nt++) {
            const int col = n0 + wn * 32 + nt * 8 + 2 * tg;
            float2 lo, hi;
            lo.x = acc[mt][nt][0] * alpha; lo.y = acc[mt][nt][1] * alpha;
            hi.x = acc[mt][nt][2] * alpha; hi.y = acc[mt][nt][3] * alpha;
            *reinterpret_cast<float2*>(Cb + (size_t)row * N + col)       = lo;
            *reinterpret_cast<float2*>(Cb + (size_t)(row + 8) * N + col) = hi;
        }
    }
}

// ---------------------------------------------------------------------------
// Pre-pass: fp32 -> fp16
// ---------------------------------------------------------------------------
__global__ __launch_bounds__(256)
void to_half_kernel(const float4* __restrict__ in, __half2* __restrict__ out, int n4)
{
    int i = blockIdx.x * blockDim.x + threadIdx.x;
    if (i < n4) {
        float4 v = in[i];
        out[2 * i]     = __float22half2_rn(make_float2(v.x, v.y));
        out[2 * i + 1] = __float22half2_rn(make_float2(v.z, v.w));
    }
}

// ---------------------------------------------------------------------------
// Transpose V [B,S,D] -> Vt [B,D,S] fp16 (K-major B operand for GEMM2)
// ---------------------------------------------------------------------------
__global__ __launch_bounds__(256)
void transpose_half_kernel(const float* __restrict__ V, __half* __restrict__ Vt)
{
    __shared__ float t[32][33];
    const int b = blockIdx.z;
    const float* Vb = V  + (size_t)b * SEQ * DIM;
    __half*      Tb = Vt + (size_t)b * DIM * SEQ;
    const int s0 = blockIdx.x * 32;
    const int d0 = blockIdx.y * 32;
    const int x = threadIdx.x, y = threadIdx.y;   // 32 x 8
#pragma unroll
    for (int i = 0; i < 32; i += 8)
        t[y + i][x] = Vb[(size_t)(s0 + y + i) * DIM + d0 + x];
    __syncthreads();
#pragma unroll
    for (int i = 0; i < 32; i += 8)
        Tb[(size_t)(d0 + y + i) * SEQ + s0 + x] = __float2half_rn(t[x][y + i]);
}

// ---------------------------------------------------------------------------
// Row softmax (len 2048, in place, fp32) + fp16 copy for GEMM2's A operand
// ---------------------------------------------------------------------------
__global__ __launch_bounds__(256)
void softmax_kernel(float* __restrict__ W, __half* __restrict__ Wh)
{
    const size_t row = blockIdx.x;
    float*  p  = W  + row * (size_t)SEQ;
    __half2* ph = reinterpret_cast<__half2*>(Wh + row * (size_t)SEQ);
    const int t = threadIdx.x;

    float4 v0 = reinterpret_cast<const float4*>(p)[t];
    float4 v1 = reinterpret_cast<const float4*>(p)[t + 256];

    float m = fmaxf(fmaxf(fmaxf(v0.x, v0.y), fmaxf(v0.z, v0.w)),
                    fmaxf(fmaxf(v1.x, v1.y), fmaxf(v1.z, v1.w)));

    __shared__ float red[8];
#pragma unroll
    for (int o = 16; o > 0; o >>= 1)
        m = fmaxf(m, __shfl_xor_sync(0xffffffffu, m, o));
    if ((t & 31) == 0) red[t >> 5] = m;
    __syncthreads();
    float rowmax = red[0];
#pragma unroll
    for (int i = 1; i < 8; i++) rowmax = fmaxf(rowmax, red[i]);
    __syncthreads();

    v0.x = __expf(v0.x - rowmax); v0.y = __expf(v0.y - rowmax);
    v0.z = __expf(v0.z - rowmax); v0.w = __expf(v0.w - rowmax);
    v1.x = __expf(v1.x - rowmax); v1.y = __expf(v1.y - rowmax);
    v1.z = __expf(v1.z - rowmax); v1.w = __expf(v1.w - rowmax);

    float s = ((v0.x + v0.y) + (v0.z + v0.w)) + ((v1.x + v1.y) + (v1.z + v1.w));
#pragma unroll
    for (int o = 16; o > 0; o >>= 1)
        s += __shfl_xor_sync(0xffffffffu, s, o);
    if ((t & 31) == 0) red[t >> 5] = s;
    __syncthreads();
    float rowsum = red[0];
#pragma unroll
    for (int i = 1; i < 8; i++) rowsum += red[i];

    const float inv = 1.0f / rowsum;
    v0.x *= inv; v0.y *= inv; v0.z *= inv; v0.w *= inv;
    v1.x *= inv; v1.y *= inv; v1.z *= inv; v1.w *= inv;

    reinterpret_cast<float4*>(p)[t]       = v0;
    reinterpret_cast<float4*>(p)[t + 256] = v1;

    ph[2 * t]           = __float22half2_rn(make_float2(v0.x, v0.y));
    ph[2 * t + 1]       = __float22half2_rn(make_float2(v0.z, v0.w));
    ph[512 + 2 * t]     = __float22half2_rn(make_float2(v1.x, v1.y));
    ph[512 + 2 * t + 1] = __float22half2_rn(make_float2(v1.z, v1.w));
}

// ---------------------------------------------------------------------------
// Launch: out = [output (B*S*D) | attention_weights (B*S*S)]
// ---------------------------------------------------------------------------
extern "C" void kernel_launch(void* const* d_in, const int* in_sizes, int n_in,
                              void* d_out, int out_size)
{
    (void)in_sizes; (void)n_in; (void)out_size;
    const float* q = (const float*)d_in[0];
    const float* k = (const float*)d_in[1];
    const float* v = (const float*)d_in[2];
    float* out = (float*)d_out;
    float* w   = out + (size_t)BATCH * SEQ * DIM;   // weights / scores region

    __half *qh, *kh, *vt, *wh;
    cudaGetSymbolAddress((void**)&qh, g_qh);
    cudaGetSymbolAddress((void**)&kh, g_kh);
    cudaGetSymbolAddress((void**)&vt, g_vt);
    cudaGetSymbolAddress((void**)&wh, g_wh);

    cudaFuncSetAttribute(gemm_h, cudaFuncAttributeMaxDynamicSharedMemorySize, HGEMM_DSMEM);

    const float inv_scale = 1.0f / sqrtf((float)SEQ);
    const int n4 = BATCH * SEQ * DIM / 4;

    // 1) convert Q, K to fp16
    to_half_kernel<<<(n4 + 255) / 256, 256>>>((const float4*)q, (__half2*)qh, n4);
    to_half_kernel<<<(n4 + 255) / 256, 256>>>((const float4*)k, (__half2*)kh, n4);

    // 2) transpose V -> Vt [B, D, S] fp16
    dim3 tg(SEQ / 32, DIM / 32, BATCH);
    transpose_half_kernel<<<tg, dim3(32, 8)>>>(v, vt);

    // 3) scores = Q K^T / sqrt(S)  (M=S, N=S, K=D)
    dim3 g1(SEQ / BN, SEQ / BM, BATCH);
    gemm_h<<<g1, NTHR, HGEMM_DSMEM>>>(qh, kh, w, SEQ, SEQ, DIM, inv_scale);

    // 4) softmax rows in place; fp16 copy to wh
    softmax_kernel<<<BATCH * SEQ, 256>>>(w, wh);

    // 5) out = W V  (M=S, N=D, K=S)
    dim3 g2(DIM / BN, SEQ / BM, BATCH);
    gemm_h<<<g2, NTHR, HGEMM_DSMEM>>>(wh, vt, out, SEQ, DIM, SEQ, 1.0f);
}

// round 7
// speedup vs baseline: 1.0496x; 1.0496x over previous
#include <cuda_runtime.h>
#include <cuda_fp16.h>
#include <cstdint>
#include <math.h>

// Problem constants: q,k,v : [B, S, D] float32
#define BATCH 8
#define SEQ   2048
#define DIM   512

// ---------------------------------------------------------------------------
// Scratch (__device__ globals; no allocation allowed)
// ---------------------------------------------------------------------------
__device__ __half g_qh[(size_t)BATCH * SEQ * DIM];   // Q in fp16
__device__ __half g_kh[(size_t)BATCH * SEQ * DIM];   // K in fp16
__device__ __half g_vt[(size_t)BATCH * DIM * SEQ];   // V transposed (K-major), fp16
__device__ __half g_wh[(size_t)BATCH * SEQ * SEQ];   // fp16 scores, then fp16 weights

__device__ __forceinline__ void ldsm_x4(uint32_t r[4], uint32_t addr) {
    asm volatile("ldmatrix.sync.aligned.m8n8.x4.shared.b16 {%0,%1,%2,%3}, [%4];"
                 : "=r"(r[0]), "=r"(r[1]), "=r"(r[2]), "=r"(r[3]) : "r"(addr));
}

// ---------------------------------------------------------------------------
// fp16 warp-MMA GEMM:  C[b] = alpha * A[b] (MxK, K-major) * B[b]^T (NxK, K-major)
// BM=128 fixed; TBN/TNTHR templated. BK=64 halves (128B rows, XOR swizzle),
// 3-stage cp.async, warp tile 64x32 (wm = wid&1, wn = wid>>1).
// OUT_HALF: store __half results (alpha applied); else float.
// ---------------------------------------------------------------------------
#define NSTG 3

template <int TBN, int TNTHR, int MINB, bool OUT_HALF>
__global__ __launch_bounds__(TNTHR, MINB)
void gemm_h(const __half* __restrict__ A, const __half* __restrict__ B,
            void* __restrict__ Cv, int M, int N, int Kd, float alpha)
{
    constexpr int A_BYTES = 128 * 128;            // BM rows x 128B
    constexpr int B_BYTES = TBN * 128;
    constexpr int STAGE_BYTES = A_BYTES + B_BYTES;
    constexpr int AI = (128 * 8) / TNTHR;         // A 16B-chunk loads per thread
    constexpr int BI = (TBN * 8) / TNTHR;         // B 16B-chunk loads per thread

    extern __shared__ char smem[];
    const uint32_t smem_b = (uint32_t)__cvta_generic_to_shared(smem);

    const int tid  = threadIdx.x;
    const int wid  = tid >> 5;
    const int lane = tid & 31;
    const int g    = lane >> 2;
    const int tg   = lane & 3;
    const int lr   = lane & 15;     // ldmatrix row-within-16
    const int lc   = lane >> 4;     // ldmatrix 16B-chunk select (0/1)

    const int wm = wid & 1;         // 0..1 (64 rows each)
    const int wn = wid >> 1;        // 32-col slices

    const int bz = blockIdx.z;
    const int n0 = blockIdx.x * TBN;
    const int m0 = blockIdx.y * 128;
    const __half* Ab = A + (size_t)bz * M * Kd;
    const __half* Bb = B + (size_t)bz * N * Kd;

    float acc[4][4][4];
#pragma unroll
    for (int i = 0; i < 4; i++)
#pragma unroll
        for (int j = 0; j < 4; j++)
#pragma unroll
            for (int r = 0; r < 4; r++)
                acc[i][j][r] = 0.0f;

    const int T = Kd / 64;

    auto load_stage = [&](int buf, int kt) {
        const int k0 = kt * 64;
        const uint32_t ab = smem_b + (uint32_t)buf * STAGE_BYTES;
        const uint32_t bb = ab + A_BYTES;
#pragma unroll
        for (int i = 0; i < AI; i++) {
            int idx = tid + i * TNTHR;
            int row = idx >> 3;
            int c   = idx & 7;
            uint32_t d = ab + (uint32_t)(row * 128 + ((c ^ (row & 7)) << 4));
            const __half* s = Ab + (size_t)(m0 + row) * Kd + k0 + c * 8;
            asm volatile("cp.async.cg.shared.global [%0], [%1], 16;" :: "r"(d), "l"(s));
        }
#pragma unroll
        for (int i = 0; i < BI; i++) {
            int idx = tid + i * TNTHR;
            int row = idx >> 3;
            int c   = idx & 7;
            uint32_t d = bb + (uint32_t)(row * 128 + ((c ^ (row & 7)) << 4));
            const __half* s = Bb + (size_t)(n0 + row) * Kd + k0 + c * 8;
            asm volatile("cp.async.cg.shared.global [%0], [%1], 16;" :: "r"(d), "l"(s));
        }
    };

#pragma unroll
    for (int s = 0; s < NSTG - 1; s++) {
        load_stage(s, s);
        asm volatile("cp.async.commit_group;" ::: "memory");
    }

    int cbuf = 0;
    int lbuf = NSTG - 1;
    for (int t = 0; t < T; t++) {
        asm volatile("cp.async.wait_group %0;" :: "n"(NSTG - 2) : "memory");
        __syncthreads();

        const int tn = t + NSTG - 1;
        if (tn < T) load_stage(lbuf, tn);
        asm volatile("cp.async.commit_group;" ::: "memory");
        lbuf = (lbuf + 1 == NSTG) ? 0 : lbuf + 1;

        const uint32_t ab = smem_b + (uint32_t)cbuf * STAGE_BYTES;
        const uint32_t bb = ab + A_BYTES;
        cbuf = (cbuf + 1 == NSTG) ? 0 : cbuf + 1;

#pragma unroll
        for (int ks = 0; ks < 4; ks++) {           // 4 k16 steps
            const int c = ks * 2 + lc;
            uint32_t a[4][4], b[2][4];
#pragma unroll
            for (int mt = 0; mt < 4; mt++) {
                int r = wm * 64 + mt * 16 + lr;
                ldsm_x4(a[mt], ab + (uint32_t)(r * 128 + ((c ^ (r & 7)) << 4)));
            }
#pragma unroll
            for (int pr = 0; pr < 2; pr++) {
                int r = wn * 32 + pr * 16 + lr;
                ldsm_x4(b[pr], bb + (uint32_t)(r * 128 + ((c ^ (r & 7)) << 4)));
            }
#pragma unroll
            for (int mt = 0; mt < 4; mt++)
#pragma unroll
                for (int nt = 0; nt < 4; nt++) {
                    const int pr = nt >> 1, od = nt & 1;
                    asm volatile(
                        "mma.sync.aligned.m16n8k16.row.col.f32.f16.f16.f32 "
                        "{%0,%1,%2,%3}, {%4,%5,%6,%7}, {%8,%9}, {%0,%1,%2,%3};"
                        : "+f"(acc[mt][nt][0]), "+f"(acc[mt][nt][1]),
                          "+f"(acc[mt][nt][2]), "+f"(acc[mt][nt][3])
                        : "r"(a[mt][0]), "r"(a[mt][1]), "r"(a[mt][2]), "r"(a[mt][3]),
                          "r"(b[pr][od]), "r"(b[pr][od + 2]));
                }
        }
    }

    // Epilogue: c0=[g][2tg], c1=[g][2tg+1], c2=[g+8][2tg], c3=[g+8][2tg+1]
    if (OUT_HALF) {
        __half* Cb = (__half*)Cv + (size_t)bz * M * N;
#pragma unroll
        for (int mt = 0; mt < 4; mt++) {
            const int row = m0 + wm * 64 + mt * 16 + g;
#pragma unroll
            for (int nt = 0; nt < 4; nt++) {
                const int col = n0 + wn * 32 + nt * 8 + 2 * tg;
                __half2 lo = __float22half2_rn(
                    make_float2(acc[mt][nt][0] * alpha, acc[mt][nt][1] * alpha));
                __half2 hi = __float22half2_rn(
                    make_float2(acc[mt][nt][2] * alpha, acc[mt][nt][3] * alpha));
                *reinterpret_cast<__half2*>(Cb + (size_t)row * N + col)       = lo;
                *reinterpret_cast<__half2*>(Cb + (size_t)(row + 8) * N + col) = hi;
            }
        }
    } else {
        float* Cb = (float*)Cv + (size_t)bz * M * N;
#pragma unroll
        for (int mt = 0; mt < 4; mt++) {
            const int row = m0 + wm * 64 + mt * 16 + g;
#pragma unroll
            for (int nt = 0; nt < 4; nt++) {
                const int col = n0 + wn * 32 + nt * 8 + 2 * tg;
                float2 lo, hi;
                lo.x = acc[mt][nt][0] * alpha; lo.y = acc[mt][nt][1] * alpha;
                hi.x = acc[mt][nt][2] * alpha; hi.y = acc[mt][nt][3] * alpha;
                *reinterpret_cast<float2*>(Cb + (size_t)row * N + col)       = lo;
                *reinterpret_cast<float2*>(Cb + (size_t)(row + 8) * N + col) = hi;
            }
        }
    }
}

// ---------------------------------------------------------------------------
// Pre-pass: fp32 -> fp16 for Q and K in one launch (blockIdx.y selects input)
// ---------------------------------------------------------------------------
__global__ __launch_bounds__(256)
void to_half_qk_kernel(const float4* __restrict__ q, const float4* __restrict__ k,
                       __half2* __restrict__ qh, __half2* __restrict__ kh, int n4)
{
    int i = blockIdx.x * blockDim.x + threadIdx.x;
    if (i >= n4) return;
    const float4* in  = blockIdx.y ? k  : q;
    __half2*      out = blockIdx.y ? kh : qh;
    float4 v = in[i];
    out[2 * i]     = __float22half2_rn(make_float2(v.x, v.y));
    out[2 * i + 1] = __float22half2_rn(make_float2(v.z, v.w));
}

// ---------------------------------------------------------------------------
// Transpose V [B,S,D] -> Vt [B,D,S] fp16 (K-major B operand for GEMM2)
// ---------------------------------------------------------------------------
__global__ __launch_bounds__(256)
void transpose_half_kernel(const float* __restrict__ V, __half* __restrict__ Vt)
{
    __shared__ float t[32][33];
    const int b = blockIdx.z;
    const float* Vb = V  + (size_t)b * SEQ * DIM;
    __half*      Tb = Vt + (size_t)b * DIM * SEQ;
    const int s0 = blockIdx.x * 32;
    const int d0 = blockIdx.y * 32;
    const int x = threadIdx.x, y = threadIdx.y;   // 32 x 8
#pragma unroll
    for (int i = 0; i < 32; i += 8)
        t[y + i][x] = Vb[(size_t)(s0 + y + i) * DIM + d0 + x];
    __syncthreads();
#pragma unroll
    for (int i = 0; i < 32; i += 8)
        Tb[(size_t)(d0 + y + i) * SEQ + s0 + x] = __float2half_rn(t[x][y + i]);
}

// ---------------------------------------------------------------------------
// Row softmax over fp16 scores (len 2048): reads fp16 scores from Sh,
// writes fp32 weights to W (d_out) and fp16 weights back in place (Sh).
// ---------------------------------------------------------------------------
__global__ __launch_bounds__(256)
void softmax_h_kernel(__half* __restrict__ Sh, float* __restrict__ W)
{
    const size_t row = blockIdx.x;
    __half* ps = Sh + row * (size_t)SEQ;
    float*  pw = W  + row * (size_t)SEQ;
    const int t = threadIdx.x;

    // 8 halves per thread (one 16B load)
    float4 raw = reinterpret_cast<const float4*>(ps)[t];
    __half2 h0 = *reinterpret_cast<__half2*>(&raw.x);
    __half2 h1 = *reinterpret_cast<__half2*>(&raw.y);
    __half2 h2 = *reinterpret_cast<__half2*>(&raw.z);
    __half2 h3 = *reinterpret_cast<__half2*>(&raw.w);
    float f[8];
    { float2 a = __half22float2(h0); f[0] = a.x; f[1] = a.y; }
    { float2 a = __half22float2(h1); f[2] = a.x; f[3] = a.y; }
    { float2 a = __half22float2(h2); f[4] = a.x; f[5] = a.y; }
    { float2 a = __half22float2(h3); f[6] = a.x; f[7] = a.y; }

    float m = f[0];
#pragma unroll
    for (int i = 1; i < 8; i++) m = fmaxf(m, f[i]);

    __shared__ float red[8];
#pragma unroll
    for (int o = 16; o > 0; o >>= 1)
        m = fmaxf(m, __shfl_xor_sync(0xffffffffu, m, o));
    if ((t & 31) == 0) red[t >> 5] = m;
    __syncthreads();
    float rowmax = red[0];
#pragma unroll
    for (int i = 1; i < 8; i++) rowmax = fmaxf(rowmax, red[i]);
    __syncthreads();

    float s = 0.0f;
#pragma unroll
    for (int i = 0; i < 8; i++) {
        f[i] = __expf(f[i] - rowmax);
        s += f[i];
    }
#pragma unroll
    for (int o = 16; o > 0; o >>= 1)
        s += __shfl_xor_sync(0xffffffffu, s, o);
    if ((t & 31) == 0) red[t >> 5] = s;
    __syncthreads();
    float rowsum = red[0];
#pragma unroll
    for (int i = 1; i < 8; i++) rowsum += red[i];

    const float inv = 1.0f / rowsum;
#pragma unroll
    for (int i = 0; i < 8; i++) f[i] *= inv;

    // fp32 weights out (two float4 stores)
    float4 o0 = make_float4(f[0], f[1], f[2], f[3]);
    float4 o1 = make_float4(f[4], f[5], f[6], f[7]);
    reinterpret_cast<float4*>(pw)[2 * t]     = o0;
    reinterpret_cast<float4*>(pw)[2 * t + 1] = o1;

    // fp16 weights in place (one 16B store)
    float4 packed;
    *reinterpret_cast<__half2*>(&packed.x) = __float22half2_rn(make_float2(f[0], f[1]));
    *reinterpret_cast<__half2*>(&packed.y) = __float22half2_rn(make_float2(f[2], f[3]));
    *reinterpret_cast<__half2*>(&packed.z) = __float22half2_rn(make_float2(f[4], f[5]));
    *reinterpret_cast<__half2*>(&packed.w) = __float22half2_rn(make_float2(f[6], f[7]));
    reinterpret_cast<float4*>(ps)[t] = packed;
}

// ---------------------------------------------------------------------------
// Launch: out = [output (B*S*D) | attention_weights (B*S*S)]
// ---------------------------------------------------------------------------
extern "C" void kernel_launch(void* const* d_in, const int* in_sizes, int n_in,
                              void* d_out, int out_size)
{
    (void)in_sizes; (void)n_in; (void)out_size;
    const float* q = (const float*)d_in[0];
    const float* k = (const float*)d_in[1];
    const float* v = (const float*)d_in[2];
    float* out = (float*)d_out;
    float* w   = out + (size_t)BATCH * SEQ * DIM;   // fp32 weights region

    __half *qh, *kh, *vt, *wh;
    cudaGetSymbolAddress((void**)&qh, g_qh);
    cudaGetSymbolAddress((void**)&kh, g_kh);
    cudaGetSymbolAddress((void**)&vt, g_vt);
    cudaGetSymbolAddress((void**)&wh, g_wh);

    const int smem1 = NSTG * (128 + 256) * 128;   // 147456
    const int smem2 = NSTG * (128 + 128) * 128;   //  98304
    cudaFuncSetAttribute((const void*)gemm_h<256, 512, 1, true>,
                         cudaFuncAttributeMaxDynamicSharedMemorySize, smem1);
    cudaFuncSetAttribute((const void*)gemm_h<128, 256, 2, false>,
                         cudaFuncAttributeMaxDynamicSharedMemorySize, smem2);

    const float inv_scale = 1.0f / sqrtf((float)SEQ);
    const int n4 = BATCH * SEQ * DIM / 4;

    // 1) convert Q, K to fp16 (single launch)
    to_half_qk_kernel<<<dim3((n4 + 255) / 256, 2), 256>>>(
        (const float4*)q, (const float4*)k, (__half2*)qh, (__half2*)kh, n4);

    // 2) transpose V -> Vt [B, D, S] fp16
    dim3 tg(SEQ / 32, DIM / 32, BATCH);
    transpose_half_kernel<<<tg, dim3(32, 8)>>>(v, vt);

    // 3) fp16 scores = Q K^T / sqrt(S) -> g_wh   (M=S, N=S, K=D)
    dim3 g1(SEQ / 256, SEQ / 128, BATCH);
    gemm_h<256, 512, 1, true><<<g1, 512, smem1>>>(qh, kh, wh, SEQ, SEQ, DIM, inv_scale);

    // 4) softmax: fp16 scores -> fp32 weights (d_out) + fp16 weights (in place)
    softmax_h_kernel<<<BATCH * SEQ, 256>>>(wh, w);

    // 5) out = W V   (M=S, N=D, K=S), 128x128 tiles, 2 CTAs/SM
    dim3 g2(DIM / 128, SEQ / 128, BATCH);
    gemm_h<128, 256, 2, false><<<g2, 256, smem2>>>(wh, vt, out, SEQ, DIM, SEQ, 1.0f);
}

// round 8
// speedup vs baseline: 1.0510x; 1.0013x over previous
#include <cuda_runtime.h>
#include <cuda_fp16.h>
#include <cstdint>
#include <math.h>

// Problem constants: q,k,v : [B, S, D] float32
#define BATCH 8
#define SEQ   2048
#define DIM   512
#define NROWS (BATCH * SEQ)        // 16384
#define NTILE 8                    // SEQ / 256 (GEMM1 n-tiles per row)

// ---------------------------------------------------------------------------
// Scratch (__device__ globals; no allocation allowed)
// ---------------------------------------------------------------------------
__device__ __half g_qh[(size_t)BATCH * SEQ * DIM];   // Q in fp16
__device__ __half g_kh[(size_t)BATCH * SEQ * DIM];   // K in fp16
__device__ __half g_vt[(size_t)BATCH * DIM * SEQ];   // V transposed (K-major), fp16
__device__ __half g_wh[(size_t)BATCH * SEQ * SEQ];   // E = exp(scores), fp16
__device__ float  g_part[(size_t)NTILE * NROWS];     // per-CTA row partial sums
__device__ float  g_inv[NROWS];                      // 1 / rowsum

__device__ __forceinline__ void ldsm_x4(uint32_t r[4], uint32_t addr) {
    asm volatile("ldmatrix.sync.aligned.m8n8.x4.shared.b16 {%0,%1,%2,%3}, [%4];"
                 : "=r"(r[0]), "=r"(r[1]), "=r"(r[2]), "=r"(r[3]) : "r"(addr));
}

// ---------------------------------------------------------------------------
// fp16 warp-MMA GEMM:  C[b] = A[b] (MxK, K-major) * B[b]^T (NxK, K-major)
// BM=128 fixed; TBN/TNTHR templated. BK=64 halves (128B rows, XOR swizzle),
// 3-stage cp.async, warp tile 64x32 (wm = wid&1, wn = wid>>1).
// EXP_OUT=true : store fp16 exp(alpha*acc), emit deterministic row partial
//                sums to part[nTile][B*S].
// EXP_OUT=false: store fp32 acc * inv_rowsum[row] (aux = inv array).
// ---------------------------------------------------------------------------
#define NSTG 3

template <int TBN, int TNTHR, int MINB, bool EXP_OUT>
__global__ __launch_bounds__(TNTHR, MINB)
void gemm_h(const __half* __restrict__ A, const __half* __restrict__ B,
            void* __restrict__ Cv, float* __restrict__ aux,
            int M, int N, int Kd, float alpha)
{
    constexpr int A_BYTES = 128 * 128;
    constexpr int B_BYTES = TBN * 128;
    constexpr int STAGE_BYTES = A_BYTES + B_BYTES;
    constexpr int AI = (128 * 8) / TNTHR;
    constexpr int BI = (TBN * 8) / TNTHR;
    constexpr int NWN = TNTHR / 64;          // warps in n-direction

    extern __shared__ char smem[];
    const uint32_t smem_b = (uint32_t)__cvta_generic_to_shared(smem);

    const int tid  = threadIdx.x;
    const int wid  = tid >> 5;
    const int lane = tid & 31;
    const int g    = lane >> 2;
    const int tg   = lane & 3;
    const int lr   = lane & 15;
    const int lc   = lane >> 4;

    const int wm = wid & 1;
    const int wn = wid >> 1;

    const int bz = blockIdx.z;
    const int n0 = blockIdx.x * TBN;
    const int m0 = blockIdx.y * 128;
    const __half* Ab = A + (size_t)bz * M * Kd;
    const __half* Bb = B + (size_t)bz * N * Kd;

    float acc[4][4][4];
#pragma unroll
    for (int i = 0; i < 4; i++)
#pragma unroll
        for (int j = 0; j < 4; j++)
#pragma unroll
            for (int r = 0; r < 4; r++)
                acc[i][j][r] = 0.0f;

    const int T = Kd / 64;

    auto load_stage = [&](int buf, int kt) {
        const int k0 = kt * 64;
        const uint32_t ab = smem_b + (uint32_t)buf * STAGE_BYTES;
        const uint32_t bb = ab + A_BYTES;
#pragma unroll
        for (int i = 0; i < AI; i++) {
            int idx = tid + i * TNTHR;
            int row = idx >> 3;
            int c   = idx & 7;
            uint32_t d = ab + (uint32_t)(row * 128 + ((c ^ (row & 7)) << 4));
            const __half* s = Ab + (size_t)(m0 + row) * Kd + k0 + c * 8;
            asm volatile("cp.async.cg.shared.global [%0], [%1], 16;" :: "r"(d), "l"(s));
        }
#pragma unroll
        for (int i = 0; i < BI; i++) {
            int idx = tid + i * TNTHR;
            int row = idx >> 3;
            int c   = idx & 7;
            uint32_t d = bb + (uint32_t)(row * 128 + ((c ^ (row & 7)) << 4));
            const __half* s = Bb + (size_t)(n0 + row) * Kd + k0 + c * 8;
            asm volatile("cp.async.cg.shared.global [%0], [%1], 16;" :: "r"(d), "l"(s));
        }
    };

#pragma unroll
    for (int s = 0; s < NSTG - 1; s++) {
        load_stage(s, s);
        asm volatile("cp.async.commit_group;" ::: "memory");
    }

    int cbuf = 0;
    int lbuf = NSTG - 1;
    for (int t = 0; t < T; t++) {
        asm volatile("cp.async.wait_group %0;" :: "n"(NSTG - 2) : "memory");
        __syncthreads();

        const int tn = t + NSTG - 1;
        if (tn < T) load_stage(lbuf, tn);
        asm volatile("cp.async.commit_group;" ::: "memory");
        lbuf = (lbuf + 1 == NSTG) ? 0 : lbuf + 1;

        const uint32_t ab = smem_b + (uint32_t)cbuf * STAGE_BYTES;
        const uint32_t bb = ab + A_BYTES;
        cbuf = (cbuf + 1 == NSTG) ? 0 : cbuf + 1;

#pragma unroll
        for (int ks = 0; ks < 4; ks++) {
            const int c = ks * 2 + lc;
            uint32_t a[4][4], b[2][4];
#pragma unroll
            for (int mt = 0; mt < 4; mt++) {
                int r = wm * 64 + mt * 16 + lr;
                ldsm_x4(a[mt], ab + (uint32_t)(r * 128 + ((c ^ (r & 7)) << 4)));
            }
#pragma unroll
            for (int pr = 0; pr < 2; pr++) {
                int r = wn * 32 + pr * 16 + lr;
                ldsm_x4(b[pr], bb + (uint32_t)(r * 128 + ((c ^ (r & 7)) << 4)));
            }
#pragma unroll
            for (int mt = 0; mt < 4; mt++)
#pragma unroll
                for (int nt = 0; nt < 4; nt++) {
                    const int pr = nt >> 1, od = nt & 1;
                    asm volatile(
                        "mma.sync.aligned.m16n8k16.row.col.f32.f16.f16.f32 "
                        "{%0,%1,%2,%3}, {%4,%5,%6,%7}, {%8,%9}, {%0,%1,%2,%3};"
                        : "+f"(acc[mt][nt][0]), "+f"(acc[mt][nt][1]),
                          "+f"(acc[mt][nt][2]), "+f"(acc[mt][nt][3])
                        : "r"(a[mt][0]), "r"(a[mt][1]), "r"(a[mt][2]), "r"(a[mt][3]),
                          "r"(b[pr][od]), "r"(b[pr][od + 2]));
                }
        }
    }

    if (EXP_OUT) {
        // Epilogue: E = exp(alpha*acc) -> fp16, + deterministic row sums.
        __half* Cb = (__half*)Cv + (size_t)bz * M * N;
        __syncthreads();                          // stage smem now dead
        float* ssum = reinterpret_cast<float*>(smem);   // [128][NWN]
#pragma unroll
        for (int mt = 0; mt < 4; mt++) {
            const int row = m0 + wm * 64 + mt * 16 + g;
            float s0 = 0.0f, s1 = 0.0f;
#pragma unroll
            for (int nt = 0; nt < 4; nt++) {
                const int col = n0 + wn * 32 + nt * 8 + 2 * tg;
                float e0 = __expf(acc[mt][nt][0] * alpha);
                float e1 = __expf(acc[mt][nt][1] * alpha);
                float e2 = __expf(acc[mt][nt][2] * alpha);
                float e3 = __expf(acc[mt][nt][3] * alpha);
                *reinterpret_cast<__half2*>(Cb + (size_t)row * N + col) =
                    __float22half2_rn(make_float2(e0, e1));
                *reinterpret_cast<__half2*>(Cb + (size_t)(row + 8) * N + col) =
                    __float22half2_rn(make_float2(e2, e3));
                s0 += e0 + e1;
                s1 += e2 + e3;
            }
            s0 += __shfl_xor_sync(0xffffffffu, s0, 1);
            s0 += __shfl_xor_sync(0xffffffffu, s0, 2);
            s1 += __shfl_xor_sync(0xffffffffu, s1, 1);
            s1 += __shfl_xor_sync(0xffffffffu, s1, 2);
            if (tg == 0) {
                const int rl = wm * 64 + mt * 16 + g;
                ssum[rl * NWN + wn]       = s0;
                ssum[(rl + 8) * NWN + wn] = s1;
            }
        }
        __syncthreads();
        if (tid < 128) {
            float tsum = 0.0f;
#pragma unroll
            for (int j = 0; j < NWN; j++) tsum += ssum[tid * NWN + j];
            aux[(size_t)blockIdx.x * NROWS + (size_t)bz * M + m0 + tid] = tsum;
        }
    } else {
        // Epilogue: fp32 out, row-scaled by inv_rowsum (alpha folded in).
        float* Cb = (float*)Cv + (size_t)bz * M * N;
        const float* invr = aux + (size_t)bz * M;
#pragma unroll
        for (int mt = 0; mt < 4; mt++) {
            const int row = m0 + wm * 64 + mt * 16 + g;
            const float i0 = __ldg(invr + row) * alpha;
            const float i1 = __ldg(invr + row + 8) * alpha;
#pragma unroll
            for (int nt = 0; nt < 4; nt++) {
                const int col = n0 + wn * 32 + nt * 8 + 2 * tg;
                float2 lo, hi;
                lo.x = acc[mt][nt][0] * i0; lo.y = acc[mt][nt][1] * i0;
                hi.x = acc[mt][nt][2] * i1; hi.y = acc[mt][nt][3] * i1;
                *reinterpret_cast<float2*>(Cb + (size_t)row * N + col)       = lo;
                *reinterpret_cast<float2*>(Cb + (size_t)(row + 8) * N + col) = hi;
            }
        }
    }
}

// ---------------------------------------------------------------------------
// Pre-pass: fp32 -> fp16 for Q and K in one launch (blockIdx.y selects input)
// ---------------------------------------------------------------------------
__global__ __launch_bounds__(256)
void to_half_qk_kernel(const float4* __restrict__ q, const float4* __restrict__ k,
                       __half2* __restrict__ qh, __half2* __restrict__ kh, int n4)
{
    int i = blockIdx.x * blockDim.x + threadIdx.x;
    if (i >= n4) return;
    const float4* in  = blockIdx.y ? k  : q;
    __half2*      out = blockIdx.y ? kh : qh;
    float4 v = in[i];
    out[2 * i]     = __float22half2_rn(make_float2(v.x, v.y));
    out[2 * i + 1] = __float22half2_rn(make_float2(v.z, v.w));
}

// ---------------------------------------------------------------------------
// Transpose V [B,S,D] -> Vt [B,D,S] fp16 (K-major B operand for GEMM2)
// ---------------------------------------------------------------------------
__global__ __launch_bounds__(256)
void transpose_half_kernel(const float* __restrict__ V, __half* __restrict__ Vt)
{
    __shared__ float t[32][33];
    const int b = blockIdx.z;
    const float* Vb = V  + (size_t)b * SEQ * DIM;
    __half*      Tb = Vt + (size_t)b * DIM * SEQ;
    const int s0 = blockIdx.x * 32;
    const int d0 = blockIdx.y * 32;
    const int x = threadIdx.x, y = threadIdx.y;   // 32 x 8
#pragma unroll
    for (int i = 0; i < 32; i += 8)
        t[y + i][x] = Vb[(size_t)(s0 + y + i) * DIM + d0 + x];
    __syncthreads();
#pragma unroll
    for (int i = 0; i < 32; i += 8)
        Tb[(size_t)(d0 + y + i) * SEQ + s0 + x] = __float2half_rn(t[x][y + i]);
}

// ---------------------------------------------------------------------------
// Finalize: inv[r] = 1 / sum_j part[j][r]   (deterministic)
// ---------------------------------------------------------------------------
__global__ __launch_bounds__(256)
void finalize_kernel(const float* __restrict__ part, float* __restrict__ inv)
{
    int i = blockIdx.x * 256 + threadIdx.x;
    float s = 0.0f;
#pragma unroll
    for (int j = 0; j < NTILE; j++) s += part[(size_t)j * NROWS + i];
    inv[i] = 1.0f / s;
}

// ---------------------------------------------------------------------------
// Normalize: fp32 weights = fp16 E * inv_rowsum  (writes d_out weights region)
// ---------------------------------------------------------------------------
__global__ __launch_bounds__(256)
void normalize_kernel(const __half* __restrict__ E, const float* __restrict__ inv,
                      float* __restrict__ W)
{
    const size_t row = blockIdx.x;
    const float iv = inv[row];
    const int t = threadIdx.x;
    float4 raw = reinterpret_cast<const float4*>(E + row * (size_t)SEQ)[t];
    float2 a = __half22float2(*reinterpret_cast<__half2*>(&raw.x));
    float2 b = __half22float2(*reinterpret_cast<__half2*>(&raw.y));
    float2 c = __half22float2(*reinterpret_cast<__half2*>(&raw.z));
    float2 d = __half22float2(*reinterpret_cast<__half2*>(&raw.w));
    float4 o0 = make_float4(a.x * iv, a.y * iv, b.x * iv, b.y * iv);
    float4 o1 = make_float4(c.x * iv, c.y * iv, d.x * iv, d.y * iv);
    float* pw = W + row * (size_t)SEQ;
    reinterpret_cast<float4*>(pw)[2 * t]     = o0;
    reinterpret_cast<float4*>(pw)[2 * t + 1] = o1;
}

// ---------------------------------------------------------------------------
// Launch: out = [output (B*S*D) | attention_weights (B*S*S)]
// Fork-join: normalize (weights) runs on a side stream, overlapped with GEMM2.
// ---------------------------------------------------------------------------
extern "C" void kernel_launch(void* const* d_in, const int* in_sizes, int n_in,
                              void* d_out, int out_size)
{
    (void)in_sizes; (void)n_in; (void)out_size;
    const float* q = (const float*)d_in[0];
    const float* k = (const float*)d_in[1];
    const float* v = (const float*)d_in[2];
    float* out = (float*)d_out;
    float* w   = out + (size_t)BATCH * SEQ * DIM;   // fp32 weights region

    __half *qh, *kh, *vt, *wh;
    float *part, *inv;
    cudaGetSymbolAddress((void**)&qh, g_qh);
    cudaGetSymbolAddress((void**)&kh, g_kh);
    cudaGetSymbolAddress((void**)&vt, g_vt);
    cudaGetSymbolAddress((void**)&wh, g_wh);
    cudaGetSymbolAddress((void**)&part, g_part);
    cudaGetSymbolAddress((void**)&inv, g_inv);

    static cudaStream_t s2 = nullptr;
    static cudaEvent_t ev1 = nullptr, ev2 = nullptr;
    if (!s2) {   // first call is the eager correctness run (not captured)
        cudaStreamCreateWithFlags(&s2, cudaStreamNonBlocking);
        cudaEventCreateWithFlags(&ev1, cudaEventDisableTiming);
        cudaEventCreateWithFlags(&ev2, cudaEventDisableTiming);
    }

    const int smem1 = NSTG * (128 + 256) * 128;   // 147456
    const int smem2 = NSTG * (128 + 128) * 128;   //  98304
    cudaFuncSetAttribute((const void*)gemm_h<256, 512, 1, true>,
                         cudaFuncAttributeMaxDynamicSharedMemorySize, smem1);
    cudaFuncSetAttribute((const void*)gemm_h<128, 256, 2, false>,
                         cudaFuncAttributeMaxDynamicSharedMemorySize, smem2);

    const float inv_scale = 1.0f / sqrtf((float)SEQ);
    const int n4 = BATCH * SEQ * DIM / 4;

    // 1) convert Q, K to fp16
    to_half_qk_kernel<<<dim3((n4 + 255) / 256, 2), 256>>>(
        (const float4*)q, (const float4*)k, (__half2*)qh, (__half2*)kh, n4);

    // 2) transpose V -> Vt [B, D, S] fp16
    dim3 tg(SEQ / 32, DIM / 32, BATCH);
    transpose_half_kernel<<<tg, dim3(32, 8)>>>(v, vt);

    // 3) E = exp(Q K^T / sqrt(S)) -> g_wh (fp16) + row partial sums
    dim3 g1(SEQ / 256, SEQ / 128, BATCH);
    gemm_h<256, 512, 1, true><<<g1, 512, smem1>>>(qh, kh, wh, part,
                                                  SEQ, SEQ, DIM, inv_scale);

    // 4) inv rowsums
    finalize_kernel<<<NROWS / 256, 256>>>(part, inv);

    // fork: normalize (fp32 weights) on s2, GEMM2 on main stream
    cudaEventRecord(ev1, 0);
    cudaStreamWaitEvent(s2, ev1, 0);
    normalize_kernel<<<NROWS, 256, 0, s2>>>(wh, inv, w);

    // 5) out = (E V) * inv_rowsum   (M=S, N=D, K=S)
    dim3 g2(DIM / 128, SEQ / 128, BATCH);
    gemm_h<128, 256, 2, false><<<g2, 256, smem2>>>(wh, vt, out, inv,
                                                   SEQ, DIM, SEQ, 1.0f);

    // join
    cudaEventRecord(ev2, s2);
    cudaStreamWaitEvent(0, ev2, 0);
}